// round 2
// baseline (speedup 1.0000x reference)
#include <cuda_runtime.h>
#include <cuda_bf16.h>
#include <math.h>

// Problem constants
#define BB 2
#define SS 4096
#define DD 512
#define HH 8
#define HD 64
#define MM (BB*SS)   // 8192 rows flattened

// -------------------- scratch (device globals; no allocation allowed) ------
__device__ float g_q[MM * DD];
__device__ float g_k[MM * DD];
__device__ float g_v[MM * DD];
__device__ float g_ao[MM * DD];

// ---------------------------------------------------------------------------
// GEMM: C[M,N] = A[M,K] * W[K,N] + bias[N]; M=8192, N=K=512.
// 128x128 block tile, BK=16, 256 threads, 8x8 microtile per thread.
// ---------------------------------------------------------------------------
#define GBM 128
#define GBN 128
#define GBK 16

__global__ __launch_bounds__(256, 2)
void gemm_bias_kernel(const float* __restrict__ A,
                      const float* __restrict__ W,
                      const float* __restrict__ bias,
                      float* __restrict__ C) {
    __shared__ float As[GBK][GBM + 4];   // transposed A tile, padded
    __shared__ float Bs[GBK][GBN + 4];   // W tile, padded

    const int tid = threadIdx.x;
    const int bm = blockIdx.y * GBM;
    const int bn = blockIdx.x * GBN;
    const int tx = tid & 15;      // 16 col groups
    const int ty = tid >> 4;      // 16 row groups

    float acc[8][8];
#pragma unroll
    for (int i = 0; i < 8; i++)
#pragma unroll
        for (int j = 0; j < 8; j++) acc[i][j] = 0.0f;

    for (int k0 = 0; k0 < DD; k0 += GBK) {
        // Load A tile 128x16 (transposed into As[k][m])
#pragma unroll
        for (int it = 0; it < 2; it++) {
            int id = tid + it * 256;          // 0..511
            int r  = id >> 2;                 // 0..127
            int c4 = (id & 3) << 2;           // 0,4,8,12
            float4 v = *(const float4*)&A[(size_t)(bm + r) * DD + k0 + c4];
            As[c4 + 0][r] = v.x;
            As[c4 + 1][r] = v.y;
            As[c4 + 2][r] = v.z;
            As[c4 + 3][r] = v.w;
        }
        // Load W tile 16x128
#pragma unroll
        for (int it = 0; it < 2; it++) {
            int id = tid + it * 256;
            int r  = id >> 5;                 // 0..15
            int c4 = (id & 31) << 2;          // 0..124
            *(float4*)&Bs[r][c4] = *(const float4*)&W[(size_t)(k0 + r) * DD + bn + c4];
        }
        __syncthreads();

#pragma unroll
        for (int k = 0; k < GBK; k++) {
            float a[8], b[8];
            float4 a0 = *(const float4*)&As[k][ty * 8];
            float4 a1 = *(const float4*)&As[k][ty * 8 + 4];
            float4 b0 = *(const float4*)&Bs[k][tx * 8];
            float4 b1 = *(const float4*)&Bs[k][tx * 8 + 4];
            a[0]=a0.x; a[1]=a0.y; a[2]=a0.z; a[3]=a0.w;
            a[4]=a1.x; a[5]=a1.y; a[6]=a1.z; a[7]=a1.w;
            b[0]=b0.x; b[1]=b0.y; b[2]=b0.z; b[3]=b0.w;
            b[4]=b1.x; b[5]=b1.y; b[6]=b1.z; b[7]=b1.w;
#pragma unroll
            for (int i = 0; i < 8; i++)
#pragma unroll
                for (int j = 0; j < 8; j++)
                    acc[i][j] = fmaf(a[i], b[j], acc[i][j]);
        }
        __syncthreads();
    }

    // Epilogue: bias add + store
#pragma unroll
    for (int i = 0; i < 8; i++) {
        int r = bm + ty * 8 + i;
#pragma unroll
        for (int j = 0; j < 8; j += 4) {
            int c = bn + tx * 8 + j;
            float4 o;
            o.x = acc[i][j + 0] + bias[c + 0];
            o.y = acc[i][j + 1] + bias[c + 1];
            o.z = acc[i][j + 2] + bias[c + 2];
            o.w = acc[i][j + 3] + bias[c + 3];
            *(float4*)&C[(size_t)r * DD + c] = o;
        }
    }
}

// ---------------------------------------------------------------------------
// Flash attention (fp32): per block: 64 queries of one (b,h); loop 64-key
// tiles with online softmax. 256 threads, 4x4 microtiles.
// Dynamic smem: Qs[64*64] + Ks[64*68] + Vs[64*68] + Ps[64*64]
// ---------------------------------------------------------------------------
#define KPAD 68
#define ATTN_SMEM ((64*64 + 64*KPAD + 64*KPAD + 64*64) * 4)

__global__ __launch_bounds__(256, 2)
void attn_kernel(const float* __restrict__ Q,
                 const float* __restrict__ K,
                 const float* __restrict__ V,
                 float* __restrict__ O) {
    extern __shared__ float sm[];
    float* Qs = sm;                       // 64*64
    float* Ks = Qs + 64 * 64;             // 64*68
    float* Vs = Ks + 64 * KPAD;           // 64*68
    float* Ps = Vs + 64 * KPAD;           // 64*64

    const int tid = threadIdx.x;
    const int tx = tid & 15;
    const int ty = tid >> 4;
    const int bh = blockIdx.y;            // b*H + h
    const int qt = blockIdx.x;            // query tile 0..63
    const int b = bh >> 3;
    const int h = bh & 7;

    const float* qbase = Q + ((size_t)(b * SS + qt * 64)) * DD + h * HD;
    const float* kbase = K + ((size_t)(b * SS)) * DD + h * HD;
    const float* vbase = V + ((size_t)(b * SS)) * DD + h * HD;

    // Load Q tile, pre-scaled by 1/sqrt(HD)
#pragma unroll
    for (int it = 0; it < 4; it++) {
        int id = tid + it * 256;          // 0..1023 -> 64 rows x 16 float4
        int r  = id >> 4;
        int c4 = (id & 15) << 2;
        float4 v = *(const float4*)&qbase[(size_t)r * DD + c4];
        Qs[r * 64 + c4 + 0] = v.x * 0.125f;
        Qs[r * 64 + c4 + 1] = v.y * 0.125f;
        Qs[r * 64 + c4 + 2] = v.z * 0.125f;
        Qs[r * 64 + c4 + 3] = v.w * 0.125f;
    }

    float m[4], l[4], o[4][4];
#pragma unroll
    for (int i = 0; i < 4; i++) {
        m[i] = -1e30f;
        l[i] = 0.0f;
#pragma unroll
        for (int j = 0; j < 4; j++) o[i][j] = 0.0f;
    }

    for (int t = 0; t < SS / 64; t++) {
        __syncthreads();   // prior iter finished reading Ks/Vs/Ps; Qs ready (t=0)
        // Load K/V tiles
#pragma unroll
        for (int it = 0; it < 4; it++) {
            int id = tid + it * 256;
            int r  = id >> 4;
            int c4 = (id & 15) << 2;
            size_t goff = (size_t)(t * 64 + r) * DD + c4;
            float4 kv = *(const float4*)&kbase[goff];
            Ks[r * KPAD + c4 + 0] = kv.x;
            Ks[r * KPAD + c4 + 1] = kv.y;
            Ks[r * KPAD + c4 + 2] = kv.z;
            Ks[r * KPAD + c4 + 3] = kv.w;
            float4 vv = *(const float4*)&vbase[goff];
            Vs[r * KPAD + c4 + 0] = vv.x;
            Vs[r * KPAD + c4 + 1] = vv.y;
            Vs[r * KPAD + c4 + 2] = vv.z;
            Vs[r * KPAD + c4 + 3] = vv.w;
        }
        __syncthreads();

        // S = Q * K^T  (4x4 per thread)
        float s[4][4];
#pragma unroll
        for (int i = 0; i < 4; i++)
#pragma unroll
            for (int j = 0; j < 4; j++) s[i][j] = 0.0f;

#pragma unroll
        for (int d4 = 0; d4 < 16; d4++) {
            float4 qv[4], kv[4];
#pragma unroll
            for (int i = 0; i < 4; i++)
                qv[i] = *(const float4*)&Qs[(ty * 4 + i) * 64 + d4 * 4];
#pragma unroll
            for (int j = 0; j < 4; j++)
                kv[j] = *(const float4*)&Ks[(tx * 4 + j) * KPAD + d4 * 4];
#pragma unroll
            for (int i = 0; i < 4; i++)
#pragma unroll
                for (int j = 0; j < 4; j++) {
                    s[i][j] = fmaf(qv[i].x, kv[j].x, s[i][j]);
                    s[i][j] = fmaf(qv[i].y, kv[j].y, s[i][j]);
                    s[i][j] = fmaf(qv[i].z, kv[j].z, s[i][j]);
                    s[i][j] = fmaf(qv[i].w, kv[j].w, s[i][j]);
                }
        }

        // Online softmax update per row
#pragma unroll
        for (int i = 0; i < 4; i++) {
            float mx = fmaxf(fmaxf(s[i][0], s[i][1]), fmaxf(s[i][2], s[i][3]));
#pragma unroll
            for (int off = 1; off < 16; off <<= 1)
                mx = fmaxf(mx, __shfl_xor_sync(0xffffffffu, mx, off));
            float mnew = fmaxf(m[i], mx);
            float corr = __expf(m[i] - mnew);
            m[i] = mnew;
            float rs = 0.0f;
#pragma unroll
            for (int j = 0; j < 4; j++) {
                s[i][j] = __expf(s[i][j] - mnew);
                rs += s[i][j];
            }
#pragma unroll
            for (int off = 1; off < 16; off <<= 1)
                rs += __shfl_xor_sync(0xffffffffu, rs, off);
            l[i] = l[i] * corr + rs;
#pragma unroll
            for (int j = 0; j < 4; j++) o[i][j] *= corr;
            // stash probabilities
#pragma unroll
            for (int j = 0; j < 4; j++)
                Ps[(ty * 4 + i) * 64 + tx * 4 + j] = s[i][j];
        }
        __syncthreads();

        // O += P * V
#pragma unroll
        for (int k4 = 0; k4 < 16; k4++) {
            float4 pv[4], vv[4];
#pragma unroll
            for (int i = 0; i < 4; i++)
                pv[i] = *(const float4*)&Ps[(ty * 4 + i) * 64 + k4 * 4];
#pragma unroll
            for (int c = 0; c < 4; c++)
                vv[c] = *(const float4*)&Vs[(k4 * 4 + c) * KPAD + tx * 4];
#pragma unroll
            for (int i = 0; i < 4; i++) {
                const float p0 = pv[i].x, p1 = pv[i].y, p2 = pv[i].z, p3 = pv[i].w;
                o[i][0] = fmaf(p0, vv[0].x, o[i][0]);
                o[i][1] = fmaf(p0, vv[0].y, o[i][1]);
                o[i][2] = fmaf(p0, vv[0].z, o[i][2]);
                o[i][3] = fmaf(p0, vv[0].w, o[i][3]);
                o[i][0] = fmaf(p1, vv[1].x, o[i][0]);
                o[i][1] = fmaf(p1, vv[1].y, o[i][1]);
                o[i][2] = fmaf(p1, vv[1].z, o[i][2]);
                o[i][3] = fmaf(p1, vv[1].w, o[i][3]);
                o[i][0] = fmaf(p2, vv[2].x, o[i][0]);
                o[i][1] = fmaf(p2, vv[2].y, o[i][1]);
                o[i][2] = fmaf(p2, vv[2].z, o[i][2]);
                o[i][3] = fmaf(p2, vv[2].w, o[i][3]);
                o[i][0] = fmaf(p3, vv[3].x, o[i][0]);
                o[i][1] = fmaf(p3, vv[3].y, o[i][1]);
                o[i][2] = fmaf(p3, vv[3].z, o[i][2]);
                o[i][3] = fmaf(p3, vv[3].w, o[i][3]);
            }
        }
    }

    // Normalize and write out (layout [B*S, D], head offset h*HD)
#pragma unroll
    for (int i = 0; i < 4; i++) {
        float invl = 1.0f / l[i];
        int row = b * SS + qt * 64 + ty * 4 + i;
        float4 ov;
        ov.x = o[i][0] * invl;
        ov.y = o[i][1] * invl;
        ov.z = o[i][2] * invl;
        ov.w = o[i][3] * invl;
        *(float4*)&O[(size_t)row * DD + h * HD + tx * 4] = ov;
    }
}

// ---------------------------------------------------------------------------
extern "C" void kernel_launch(void* const* d_in, const int* in_sizes, int n_in,
                              void* d_out, int out_size) {
    const float* x  = (const float*)d_in[0];
    const float* y  = (const float*)d_in[1];
    const float* z  = (const float*)d_in[2];
    const float* Wq = (const float*)d_in[3];
    const float* bq = (const float*)d_in[4];
    const float* Wk = (const float*)d_in[5];
    const float* bk = (const float*)d_in[6];
    const float* Wv = (const float*)d_in[7];
    const float* bv = (const float*)d_in[8];
    const float* Wp = (const float*)d_in[9];
    const float* bp = (const float*)d_in[10];

    float *q, *k, *v, *ao;
    cudaGetSymbolAddress((void**)&q,  g_q);
    cudaGetSymbolAddress((void**)&k,  g_k);
    cudaGetSymbolAddress((void**)&v,  g_v);
    cudaGetSymbolAddress((void**)&ao, g_ao);

    cudaFuncSetAttribute(attn_kernel,
                         cudaFuncAttributeMaxDynamicSharedMemorySize, ATTN_SMEM);

    dim3 gGrid(DD / GBN, MM / GBM);   // (4, 64)
    gemm_bias_kernel<<<gGrid, 256>>>(x, Wq, bq, q);
    gemm_bias_kernel<<<gGrid, 256>>>(y, Wk, bk, k);
    gemm_bias_kernel<<<gGrid, 256>>>(z, Wv, bv, v);

    dim3 aGrid(SS / 64, BB * HH);     // (64, 16)
    attn_kernel<<<aGrid, 256, ATTN_SMEM>>>(q, k, v, ao);

    gemm_bias_kernel<<<gGrid, 256>>>(ao, Wp, bp, (float*)d_out);
}

// round 3
// speedup vs baseline: 1.5959x; 1.5959x over previous
#include <cuda_runtime.h>
#include <math.h>

#define BB 2
#define SS 4096
#define DD 512
#define HH 8
#define HD 64
#define MM (BB*SS)

typedef unsigned long long ull;

// ---- packed f32x2 helpers (FFMA2: 2x fp32 FMA per instruction) ------------
__device__ __forceinline__ ull ffma2(ull a, ull b, ull c) {
    ull d;
    asm("fma.rn.f32x2 %0, %1, %2, %3;" : "=l"(d) : "l"(a), "l"(b), "l"(c));
    return d;
}
__device__ __forceinline__ ull fmul2(ull a, ull b) {
    ull d;
    asm("mul.rn.f32x2 %0, %1, %2;" : "=l"(d) : "l"(a), "l"(b));
    return d;
}
__device__ __forceinline__ ull dup2(float v) {
    ull d;
    asm("mov.b64 %0, {%1, %1};" : "=l"(d) : "f"(v));
    return d;
}
__device__ __forceinline__ float2 unpk(ull d) {
    float2 r;
    asm("mov.b64 {%0, %1}, %2;" : "=f"(r.x), "=f"(r.y) : "l"(d));
    return r;
}

// -------------------- scratch (device globals) -----------------------------
__device__ float g_q[MM * DD];
__device__ float g_k[MM * DD];
__device__ float g_v[MM * DD];
__device__ float g_ao[MM * DD];

// ---------------------------------------------------------------------------
// GEMM: C[M,N] = A[M,K]*W[K,N] + bias; 128x128 tile, BK=16, 256 thr.
// Per thread: 8 rows (ty+16i), 8 cols (4tx..4tx+3, 64+4tx..+3) as 4 f32x2 pairs.
// ---------------------------------------------------------------------------
#define GBM 128
#define GBN 128
#define GBK 16
#define APAD 20
#define BPAD 132

__global__ __launch_bounds__(256, 2)
void gemm_bias_kernel(const float* __restrict__ A,
                      const float* __restrict__ W,
                      const float* __restrict__ bias,
                      float* __restrict__ C) {
    __shared__ float As[GBM * APAD];
    __shared__ float Bs[GBK * BPAD];

    const int tid = threadIdx.x;
    const int tx = tid & 15;
    const int ty = tid >> 4;
    const int bm = blockIdx.y * GBM;
    const int bn = blockIdx.x * GBN;

    ull acc[8][4];
#pragma unroll
    for (int i = 0; i < 8; i++)
#pragma unroll
        for (int j = 0; j < 4; j++) acc[i][j] = 0ull;

    for (int k0 = 0; k0 < DD; k0 += GBK) {
#pragma unroll
        for (int it = 0; it < 2; it++) {
            int id = tid + it * 256;          // 0..511
            int r  = id >> 2;                 // 0..127
            int c4 = (id & 3) << 2;           // 0,4,8,12
            *(float4*)&As[r * APAD + c4] =
                *(const float4*)&A[(size_t)(bm + r) * DD + k0 + c4];
        }
#pragma unroll
        for (int it = 0; it < 2; it++) {
            int id = tid + it * 256;
            int r  = id >> 5;                 // 0..15
            int c4 = (id & 31) << 2;          // 0..124
            *(float4*)&Bs[r * BPAD + c4] =
                *(const float4*)&W[(size_t)(k0 + r) * DD + bn + c4];
        }
        __syncthreads();

#pragma unroll
        for (int k4 = 0; k4 < 4; k4++) {
            float4 av[8];
#pragma unroll
            for (int i = 0; i < 8; i++)
                av[i] = *(const float4*)&As[(ty + 16 * i) * APAD + k4 * 4];
#pragma unroll
            for (int c = 0; c < 4; c++) {
                int k = k4 * 4 + c;
                ulonglong2 b0 = *(const ulonglong2*)&Bs[k * BPAD + 4 * tx];
                ulonglong2 b1 = *(const ulonglong2*)&Bs[k * BPAD + 64 + 4 * tx];
#pragma unroll
                for (int i = 0; i < 8; i++) {
                    float a = (c == 0) ? av[i].x : (c == 1) ? av[i].y
                                       : (c == 2) ? av[i].z : av[i].w;
                    ull ad = dup2(a);
                    acc[i][0] = ffma2(ad, b0.x, acc[i][0]);
                    acc[i][1] = ffma2(ad, b0.y, acc[i][1]);
                    acc[i][2] = ffma2(ad, b1.x, acc[i][2]);
                    acc[i][3] = ffma2(ad, b1.y, acc[i][3]);
                }
            }
        }
        __syncthreads();
    }

    float4 bs0 = *(const float4*)&bias[bn + 4 * tx];
    float4 bs1 = *(const float4*)&bias[bn + 64 + 4 * tx];
#pragma unroll
    for (int i = 0; i < 8; i++) {
        int r = bm + ty + 16 * i;
        float2 p0 = unpk(acc[i][0]), p1 = unpk(acc[i][1]);
        float2 p2 = unpk(acc[i][2]), p3 = unpk(acc[i][3]);
        float4 o0 = make_float4(p0.x + bs0.x, p0.y + bs0.y, p1.x + bs0.z, p1.y + bs0.w);
        float4 o1 = make_float4(p2.x + bs1.x, p2.y + bs1.y, p3.x + bs1.z, p3.y + bs1.w);
        *(float4*)&C[(size_t)r * DD + bn + 4 * tx]      = o0;
        *(float4*)&C[(size_t)r * DD + bn + 64 + 4 * tx] = o1;
    }
}

// ---------------------------------------------------------------------------
// Flash attention, f32x2 packed. Block: 128 queries x full K loop in 64-key
// tiles. 256 threads (16x16). Per thread: 8 q rows (ty+16i), 4 k cols
// (tx+16j) for S; 4 d cols (tx*4..+3) as 2 pairs for O.
// ---------------------------------------------------------------------------
#define AQ 128
#define AKT 64
#define PADA 68
#define ATTN_SMEM ((AQ*PADA + AKT*PADA + AKT*PADA + AQ*PADA) * 4)

__global__ __launch_bounds__(256, 1)
void attn_kernel(const float* __restrict__ Q,
                 const float* __restrict__ K,
                 const float* __restrict__ V,
                 float* __restrict__ O) {
    extern __shared__ float sm[];
    float* Qs = sm;                          // 128 x 68
    float* Ks = Qs + AQ * PADA;              // 64 x 68
    float* Vs = Ks + AKT * PADA;             // 64 x 68
    float* Ps = Vs + AKT * PADA;             // 128 x 68

    const int tid = threadIdx.x;
    const int tx = tid & 15;
    const int ty = tid >> 4;
    const int bh = blockIdx.y;
    const int qt = blockIdx.x;
    const int b = bh >> 3;
    const int h = bh & 7;

    const float* qbase = Q + ((size_t)(b * SS + qt * AQ)) * DD + h * HD;
    const float* kbase = K + ((size_t)(b * SS)) * DD + h * HD;
    const float* vbase = V + ((size_t)(b * SS)) * DD + h * HD;

    // Load Q tile (scaled by 1/sqrt(HD))
#pragma unroll
    for (int it = 0; it < 8; it++) {
        int id = tid + it * 256;             // 0..2047
        int r  = id >> 4;                    // 0..127
        int c4 = (id & 15) << 2;
        float4 v = *(const float4*)&qbase[(size_t)r * DD + c4];
        float4 s = make_float4(v.x * 0.125f, v.y * 0.125f, v.z * 0.125f, v.w * 0.125f);
        *(float4*)&Qs[r * PADA + c4] = s;
    }

    float m[8], l[8];
    ull o2[8][2];
#pragma unroll
    for (int i = 0; i < 8; i++) {
        m[i] = -1e30f; l[i] = 0.0f;
        o2[i][0] = 0ull; o2[i][1] = 0ull;
    }

    for (int t = 0; t < SS / AKT; t++) {
        __syncthreads();                     // prev PV done; Qs ready (t=0)
#pragma unroll
        for (int it = 0; it < 4; it++) {
            int id = tid + it * 256;
            int r  = id >> 4;                // 0..63
            int c4 = (id & 15) << 2;
            size_t goff = (size_t)(t * AKT + r) * DD + c4;
            *(float4*)&Ks[r * PADA + c4] = *(const float4*)&kbase[goff];
            *(float4*)&Vs[r * PADA + c4] = *(const float4*)&vbase[goff];
        }
        __syncthreads();

        // S = Q*K^T : pairs along d, pair-accumulators
        ull s2[8][4];
#pragma unroll
        for (int i = 0; i < 8; i++)
#pragma unroll
            for (int j = 0; j < 4; j++) s2[i][j] = 0ull;

#pragma unroll
        for (int d4 = 0; d4 < 16; d4++) {
            ulonglong2 qv[8], kv[4];
#pragma unroll
            for (int i = 0; i < 8; i++)
                qv[i] = *(const ulonglong2*)&Qs[(ty + 16 * i) * PADA + d4 * 4];
#pragma unroll
            for (int j = 0; j < 4; j++)
                kv[j] = *(const ulonglong2*)&Ks[(tx + 16 * j) * PADA + d4 * 4];
#pragma unroll
            for (int i = 0; i < 8; i++)
#pragma unroll
                for (int j = 0; j < 4; j++) {
                    s2[i][j] = ffma2(qv[i].x, kv[j].x, s2[i][j]);
                    s2[i][j] = ffma2(qv[i].y, kv[j].y, s2[i][j]);
                }
        }

        // Online softmax (rows i, reduce over 16 tx lanes)
#pragma unroll
        for (int i = 0; i < 8; i++) {
            float s[4];
#pragma unroll
            for (int j = 0; j < 4; j++) {
                float2 p = unpk(s2[i][j]);
                s[j] = p.x + p.y;
            }
            float mx = fmaxf(fmaxf(s[0], s[1]), fmaxf(s[2], s[3]));
#pragma unroll
            for (int off = 1; off < 16; off <<= 1)
                mx = fmaxf(mx, __shfl_xor_sync(0xffffffffu, mx, off));
            float mnew = fmaxf(m[i], mx);
            float corr = __expf(m[i] - mnew);
            m[i] = mnew;
            float rs = 0.0f;
#pragma unroll
            for (int j = 0; j < 4; j++) {
                s[j] = __expf(s[j] - mnew);
                rs += s[j];
            }
#pragma unroll
            for (int off = 1; off < 16; off <<= 1)
                rs += __shfl_xor_sync(0xffffffffu, rs, off);
            l[i] = l[i] * corr + rs;
            ull cd = dup2(corr);
            o2[i][0] = fmul2(o2[i][0], cd);
            o2[i][1] = fmul2(o2[i][1], cd);
#pragma unroll
            for (int j = 0; j < 4; j++)
                Ps[(ty + 16 * i) * PADA + tx + 16 * j] = s[j];
        }
        __syncthreads();

        // O += P*V : pairs along d, P dup'd
#pragma unroll
        for (int k4 = 0; k4 < AKT / 4; k4++) {
            float4 pv[8];
#pragma unroll
            for (int i = 0; i < 8; i++)
                pv[i] = *(const float4*)&Ps[(ty + 16 * i) * PADA + k4 * 4];
#pragma unroll
            for (int c = 0; c < 4; c++) {
                ulonglong2 vv = *(const ulonglong2*)&Vs[(k4 * 4 + c) * PADA + tx * 4];
#pragma unroll
                for (int i = 0; i < 8; i++) {
                    float p = (c == 0) ? pv[i].x : (c == 1) ? pv[i].y
                                       : (c == 2) ? pv[i].z : pv[i].w;
                    ull pd = dup2(p);
                    o2[i][0] = ffma2(pd, vv.x, o2[i][0]);
                    o2[i][1] = ffma2(pd, vv.y, o2[i][1]);
                }
            }
        }
    }

    // Epilogue
#pragma unroll
    for (int i = 0; i < 8; i++) {
        float invl = 1.0f / l[i];
        int row = b * SS + qt * AQ + ty + 16 * i;
        float2 a = unpk(o2[i][0]);
        float2 c = unpk(o2[i][1]);
        float4 ov = make_float4(a.x * invl, a.y * invl, c.x * invl, c.y * invl);
        *(float4*)&O[(size_t)row * DD + h * HD + tx * 4] = ov;
    }
}

// ---------------------------------------------------------------------------
extern "C" void kernel_launch(void* const* d_in, const int* in_sizes, int n_in,
                              void* d_out, int out_size) {
    const float* x  = (const float*)d_in[0];
    const float* y  = (const float*)d_in[1];
    const float* z  = (const float*)d_in[2];
    const float* Wq = (const float*)d_in[3];
    const float* bq = (const float*)d_in[4];
    const float* Wk = (const float*)d_in[5];
    const float* bk = (const float*)d_in[6];
    const float* Wv = (const float*)d_in[7];
    const float* bv = (const float*)d_in[8];
    const float* Wp = (const float*)d_in[9];
    const float* bp = (const float*)d_in[10];

    float *q, *k, *v, *ao;
    cudaGetSymbolAddress((void**)&q,  g_q);
    cudaGetSymbolAddress((void**)&k,  g_k);
    cudaGetSymbolAddress((void**)&v,  g_v);
    cudaGetSymbolAddress((void**)&ao, g_ao);

    cudaFuncSetAttribute(attn_kernel,
                         cudaFuncAttributeMaxDynamicSharedMemorySize, ATTN_SMEM);

    dim3 gGrid(DD / GBN, MM / GBM);   // (4, 64)
    gemm_bias_kernel<<<gGrid, 256>>>(x, Wq, bq, q);
    gemm_bias_kernel<<<gGrid, 256>>>(y, Wk, bk, k);
    gemm_bias_kernel<<<gGrid, 256>>>(z, Wv, bv, v);

    dim3 aGrid(SS / AQ, BB * HH);     // (32, 16)
    attn_kernel<<<aGrid, 256, ATTN_SMEM>>>(q, k, v, ao);

    gemm_bias_kernel<<<gGrid, 256>>>(ao, Wp, bp, (float*)d_out);
}

// round 7
// speedup vs baseline: 2.6671x; 1.6712x over previous
#include <cuda_runtime.h>
#include <cuda_bf16.h>
#include <cstdint>
#include <math.h>

#define BB 2
#define SS 4096
#define DD 512
#define HH 8
#define HD 64
#define MM (BB*SS)

typedef unsigned int uint;
typedef unsigned long long ull;

// ---- packed f32x2 helpers (for the SIMT GEMMs) ----------------------------
__device__ __forceinline__ ull ffma2(ull a, ull b, ull c) {
    ull d;
    asm("fma.rn.f32x2 %0, %1, %2, %3;" : "=l"(d) : "l"(a), "l"(b), "l"(c));
    return d;
}
__device__ __forceinline__ ull dup2(float v) {
    ull d;
    asm("mov.b64 %0, {%1, %1};" : "=l"(d) : "f"(v));
    return d;
}
__device__ __forceinline__ float2 unpk(ull d) {
    float2 r;
    asm("mov.b64 {%0, %1}, %2;" : "=f"(r.x), "=f"(r.y) : "l"(d));
    return r;
}

// -------------------- scratch (device globals) -----------------------------
__device__ float g_q[MM * DD];
__device__ float g_k[MM * DD];
__device__ float g_v[MM * DD];
__device__ float g_ao[MM * DD];

// ---------------------------------------------------------------------------
// GEMM: C = A*W + bias (f32x2 packed; unchanged from R2)
// ---------------------------------------------------------------------------
#define GBM 128
#define GBN 128
#define GBK 16
#define APAD 20
#define BPAD 132

__global__ __launch_bounds__(256, 2)
void gemm_bias_kernel(const float* __restrict__ A,
                      const float* __restrict__ W,
                      const float* __restrict__ bias,
                      float* __restrict__ C) {
    __shared__ float As[GBM * APAD];
    __shared__ float Bs[GBK * BPAD];

    const int tid = threadIdx.x;
    const int tx = tid & 15;
    const int ty = tid >> 4;
    const int bm = blockIdx.y * GBM;
    const int bn = blockIdx.x * GBN;

    ull acc[8][4];
#pragma unroll
    for (int i = 0; i < 8; i++)
#pragma unroll
        for (int j = 0; j < 4; j++) acc[i][j] = 0ull;

    for (int k0 = 0; k0 < DD; k0 += GBK) {
#pragma unroll
        for (int it = 0; it < 2; it++) {
            int id = tid + it * 256;
            int r  = id >> 2;
            int c4 = (id & 3) << 2;
            *(float4*)&As[r * APAD + c4] =
                *(const float4*)&A[(size_t)(bm + r) * DD + k0 + c4];
        }
#pragma unroll
        for (int it = 0; it < 2; it++) {
            int id = tid + it * 256;
            int r  = id >> 5;
            int c4 = (id & 31) << 2;
            *(float4*)&Bs[r * BPAD + c4] =
                *(const float4*)&W[(size_t)(k0 + r) * DD + bn + c4];
        }
        __syncthreads();

#pragma unroll
        for (int k4 = 0; k4 < 4; k4++) {
            float4 av[8];
#pragma unroll
            for (int i = 0; i < 8; i++)
                av[i] = *(const float4*)&As[(ty + 16 * i) * APAD + k4 * 4];
#pragma unroll
            for (int c = 0; c < 4; c++) {
                int k = k4 * 4 + c;
                ulonglong2 b0 = *(const ulonglong2*)&Bs[k * BPAD + 4 * tx];
                ulonglong2 b1 = *(const ulonglong2*)&Bs[k * BPAD + 64 + 4 * tx];
#pragma unroll
                for (int i = 0; i < 8; i++) {
                    float a = (c == 0) ? av[i].x : (c == 1) ? av[i].y
                                       : (c == 2) ? av[i].z : av[i].w;
                    ull ad = dup2(a);
                    acc[i][0] = ffma2(ad, b0.x, acc[i][0]);
                    acc[i][1] = ffma2(ad, b0.y, acc[i][1]);
                    acc[i][2] = ffma2(ad, b1.x, acc[i][2]);
                    acc[i][3] = ffma2(ad, b1.y, acc[i][3]);
                }
            }
        }
        __syncthreads();
    }

    float4 bs0 = *(const float4*)&bias[bn + 4 * tx];
    float4 bs1 = *(const float4*)&bias[bn + 64 + 4 * tx];
#pragma unroll
    for (int i = 0; i < 8; i++) {
        int r = bm + ty + 16 * i;
        float2 p0 = unpk(acc[i][0]), p1 = unpk(acc[i][1]);
        float2 p2 = unpk(acc[i][2]), p3 = unpk(acc[i][3]);
        float4 o0 = make_float4(p0.x + bs0.x, p0.y + bs0.y, p1.x + bs0.z, p1.y + bs0.w);
        float4 o1 = make_float4(p2.x + bs1.x, p2.y + bs1.y, p3.x + bs1.z, p3.y + bs1.w);
        *(float4*)&C[(size_t)r * DD + bn + 4 * tx]      = o0;
        *(float4*)&C[(size_t)r * DD + bn + 64 + 4 * tx] = o1;
    }
}

// ===========================================================================
// mma.sync (m16n8k16 bf16, hi/lo compensated) flash attention
// ===========================================================================

__device__ __forceinline__ uint smem_u32(const void* p) {
    uint a;
    asm("{ .reg .u64 t; cvta.to.shared.u64 t, %1; cvt.u32.u64 %0, t; }"
        : "=r"(a) : "l"(p));
    return a;
}
__device__ __forceinline__ void ldm_x4(uint* r, uint a) {
    asm volatile("ldmatrix.sync.aligned.m8n8.x4.shared.b16 {%0,%1,%2,%3}, [%4];"
                 : "=r"(r[0]), "=r"(r[1]), "=r"(r[2]), "=r"(r[3]) : "r"(a));
}
__device__ __forceinline__ void ldm_x2(uint& r0, uint& r1, uint a) {
    asm volatile("ldmatrix.sync.aligned.m8n8.x2.shared.b16 {%0,%1}, [%2];"
                 : "=r"(r0), "=r"(r1) : "r"(a));
}
__device__ __forceinline__ void ldm_x2t(uint& r0, uint& r1, uint a) {
    asm volatile("ldmatrix.sync.aligned.m8n8.x2.trans.shared.b16 {%0,%1}, [%2];"
                 : "=r"(r0), "=r"(r1) : "r"(a));
}
__device__ __forceinline__ void mma16816(float* d, const uint* a, uint b0, uint b1) {
    asm volatile("mma.sync.aligned.m16n8k16.row.col.f32.bf16.bf16.f32 "
                 "{%0,%1,%2,%3}, {%4,%5,%6,%7}, {%8,%9}, {%0,%1,%2,%3};"
                 : "+f"(d[0]), "+f"(d[1]), "+f"(d[2]), "+f"(d[3])
                 : "r"(a[0]), "r"(a[1]), "r"(a[2]), "r"(a[3]), "r"(b0), "r"(b1));
}
// split a,b into (hi bf16 pair, lo residual bf16 pair), packed lo-elem-in-low-16
__device__ __forceinline__ void hl2(float a, float b, uint& hi2, uint& lo2) {
    __nv_bfloat16 ah = __float2bfloat16(a), bh = __float2bfloat16(b);
    float ar = a - __bfloat162float(ah);
    float br = b - __bfloat162float(bh);
    hi2 = (uint)__bfloat16_as_ushort(ah) | ((uint)__bfloat16_as_ushort(bh) << 16);
    lo2 = (uint)__bfloat16_as_ushort(__float2bfloat16(ar)) |
          ((uint)__bfloat16_as_ushort(__float2bfloat16(br)) << 16);
}
__device__ __forceinline__ void split_st(char* dh, char* dl, float4 v) {
    uint hx, lx, hy, ly;
    hl2(v.x, v.y, hx, lx);
    hl2(v.z, v.w, hy, ly);
    *(uint2*)dh = make_uint2(hx, hy);
    *(uint2*)dl = make_uint2(lx, ly);
}

// smem layout: rows of 64 halves padded to 72 (144 B: 16B-aligned, 4-bank stride)
#define RPB 144
#define OFF_QH 0
#define OFF_QL (64 * RPB)        // 9216
#define OFF_KH (2 * 64 * RPB)    // 18432
#define OFF_KL (3 * 64 * RPB)
#define OFF_VH (4 * 64 * RPB)
#define OFF_VL (5 * 64 * RPB)
#define ATTN_SMEM_M (6 * 64 * RPB)  // 55296

__global__ __launch_bounds__(128)
void attn_mma_kernel(const float* __restrict__ Q,
                     const float* __restrict__ K,
                     const float* __restrict__ V,
                     float* __restrict__ O) {
    extern __shared__ char sm[];
    const uint sb = smem_u32(sm);
    const int tid = threadIdx.x;
    const int lane = tid & 31;
    const int w = tid >> 5;

    const int bh = blockIdx.y;
    const int qt = blockIdx.x;
    const int b = bh >> 3;
    const int h = bh & 7;

    const float* qbase = Q + ((size_t)(b * SS + qt * 64)) * DD + h * HD;
    const float* kbase = K + ((size_t)(b * SS)) * DD + h * HD;
    const float* vbase = V + ((size_t)(b * SS)) * DD + h * HD;

    // ---- load Q tile (64x64), scale 1/8, split hi/lo ----
#pragma unroll
    for (int it = 0; it < 8; it++) {
        int id = tid + it * 128;          // 0..1023 = 64 rows x 16 float4
        int r  = id >> 4;
        int c4 = (id & 15) << 2;
        float4 v = *(const float4*)&qbase[(size_t)r * DD + c4];
        v.x *= 0.125f; v.y *= 0.125f; v.z *= 0.125f; v.w *= 0.125f;
        split_st(sm + OFF_QH + r * RPB + c4 * 2,
                 sm + OFF_QL + r * RPB + c4 * 2, v);
    }
    __syncthreads();

    // ---- Q fragments (per warp: rows 16w..16w+15, 4 k-steps, hi/lo) ----
    uint qh[4][4], ql[4][4];
    {
        uint qoff = sb + OFF_QH
                  + (uint)((16 * w + (lane & 7) + 8 * ((lane >> 3) & 1)) * RPB)
                  + (uint)(16 * ((lane >> 4) & 1));
#pragma unroll
        for (int s = 0; s < 4; s++) {
            ldm_x4(qh[s], qoff + 32 * s);
            ldm_x4(ql[s], qoff + (OFF_QL - OFF_QH) + 32 * s);
        }
    }

    const uint koff = sb + OFF_KH + (uint)((lane & 7) * RPB)
                    + (uint)(((lane >> 3) & 1) * 16);
    const uint voff = sb + OFF_VH
                    + (uint)(((lane & 7) + 8 * ((lane >> 3) & 1)) * RPB);

    float m0 = -1e30f, m1 = -1e30f, l0 = 0.0f, l1 = 0.0f;
    float o[8][4];
#pragma unroll
    for (int j = 0; j < 8; j++)
#pragma unroll
        for (int c = 0; c < 4; c++) o[j][c] = 0.0f;

    for (int t = 0; t < SS / 64; t++) {
        __syncthreads();   // prior PV reads done before overwrite
        // ---- load K,V tiles (64x64 each), split hi/lo ----
#pragma unroll
        for (int it = 0; it < 8; it++) {
            int id = tid + it * 128;
            int r  = id >> 4;
            int c4 = (id & 15) << 2;
            size_t goff = (size_t)(t * 64 + r) * DD + c4;
            float4 kv = *(const float4*)&kbase[goff];
            split_st(sm + OFF_KH + r * RPB + c4 * 2,
                     sm + OFF_KL + r * RPB + c4 * 2, kv);
            float4 vv = *(const float4*)&vbase[goff];
            split_st(sm + OFF_VH + r * RPB + c4 * 2,
                     sm + OFF_VL + r * RPB + c4 * 2, vv);
        }
        __syncthreads();

        // ---- S = Q·K^T (hi*hi + hi*lo + lo*hi) ----
        float sacc[8][4];
#pragma unroll
        for (int j = 0; j < 8; j++)
#pragma unroll
            for (int c = 0; c < 4; c++) sacc[j][c] = 0.0f;

#pragma unroll
        for (int j = 0; j < 8; j++) {
            uint a0 = koff + (uint)(j * 8 * RPB);
#pragma unroll
            for (int s = 0; s < 4; s++) {
                uint kh0, kh1, kl0, kl1;
                ldm_x2(kh0, kh1, a0 + 32 * s);
                ldm_x2(kl0, kl1, a0 + (OFF_KL - OFF_KH) + 32 * s);
                mma16816(sacc[j], qh[s], kh0, kh1);
                mma16816(sacc[j], qh[s], kl0, kl1);
                mma16816(sacc[j], ql[s], kh0, kh1);
            }
        }

        // ---- online softmax (rows g, g+8; 4-lane quad shares a row) ----
        float mx0 = -1e30f, mx1 = -1e30f;
#pragma unroll
        for (int j = 0; j < 8; j++) {
            mx0 = fmaxf(mx0, fmaxf(sacc[j][0], sacc[j][1]));
            mx1 = fmaxf(mx1, fmaxf(sacc[j][2], sacc[j][3]));
        }
        mx0 = fmaxf(mx0, __shfl_xor_sync(0xffffffffu, mx0, 1));
        mx0 = fmaxf(mx0, __shfl_xor_sync(0xffffffffu, mx0, 2));
        mx1 = fmaxf(mx1, __shfl_xor_sync(0xffffffffu, mx1, 1));
        mx1 = fmaxf(mx1, __shfl_xor_sync(0xffffffffu, mx1, 2));
        float mn0 = fmaxf(m0, mx0), mn1 = fmaxf(m1, mx1);
        float c0 = __expf(m0 - mn0), c1 = __expf(m1 - mn1);
        m0 = mn0; m1 = mn1;
        float rs0 = 0.0f, rs1 = 0.0f;
#pragma unroll
        for (int j = 0; j < 8; j++) {
            sacc[j][0] = __expf(sacc[j][0] - mn0);
            sacc[j][1] = __expf(sacc[j][1] - mn0);
            sacc[j][2] = __expf(sacc[j][2] - mn1);
            sacc[j][3] = __expf(sacc[j][3] - mn1);
            rs0 += sacc[j][0] + sacc[j][1];
            rs1 += sacc[j][2] + sacc[j][3];
        }
        rs0 += __shfl_xor_sync(0xffffffffu, rs0, 1);
        rs0 += __shfl_xor_sync(0xffffffffu, rs0, 2);
        rs1 += __shfl_xor_sync(0xffffffffu, rs1, 1);
        rs1 += __shfl_xor_sync(0xffffffffu, rs1, 2);
        l0 = l0 * c0 + rs0;
        l1 = l1 * c1 + rs1;
#pragma unroll
        for (int j = 0; j < 8; j++) {
            o[j][0] *= c0; o[j][1] *= c0;
            o[j][2] *= c1; o[j][3] *= c1;
        }

        // ---- P fragments (C-layout of S == A-layout of PV) ----
        uint ph[4][4], pl[4][4];
#pragma unroll
        for (int s = 0; s < 4; s++) {
            hl2(sacc[2 * s][0],     sacc[2 * s][1],     ph[s][0], pl[s][0]);
            hl2(sacc[2 * s][2],     sacc[2 * s][3],     ph[s][1], pl[s][1]);
            hl2(sacc[2 * s + 1][0], sacc[2 * s + 1][1], ph[s][2], pl[s][2]);
            hl2(sacc[2 * s + 1][2], sacc[2 * s + 1][3], ph[s][3], pl[s][3]);
        }

        // ---- O += P·V (hi*hi + hi*lo + lo*hi), V via ldmatrix.trans ----
#pragma unroll
        for (int j = 0; j < 8; j++) {
#pragma unroll
            for (int s = 0; s < 4; s++) {
                uint a0 = voff + (uint)(s * 16 * RPB) + (uint)(16 * j);
                uint vh0, vh1, vl0, vl1;
                ldm_x2t(vh0, vh1, a0);
                ldm_x2t(vl0, vl1, a0 + (OFF_VL - OFF_VH));
                mma16816(o[j], ph[s], vh0, vh1);
                mma16816(o[j], ph[s], vl0, vl1);
                mma16816(o[j], pl[s], vh0, vh1);
            }
        }
    }

    // ---- epilogue ----
    {
        float inv0 = 1.0f / l0, inv1 = 1.0f / l1;
        int g  = lane >> 2;
        int tq = lane & 3;
        size_t row0 = (size_t)(b * SS + qt * 64 + 16 * w + g);
        size_t row1 = row0 + 8;
        float* o0p = O + row0 * DD + h * HD + 2 * tq;
        float* o1p = O + row1 * DD + h * HD + 2 * tq;
#pragma unroll
        for (int j = 0; j < 8; j++) {
            *(float2*)(o0p + 8 * j) = make_float2(o[j][0] * inv0, o[j][1] * inv0);
            *(float2*)(o1p + 8 * j) = make_float2(o[j][2] * inv1, o[j][3] * inv1);
        }
    }
}

// ---------------------------------------------------------------------------
extern "C" void kernel_launch(void* const* d_in, const int* in_sizes, int n_in,
                              void* d_out, int out_size) {
    const float* x  = (const float*)d_in[0];
    const float* y  = (const float*)d_in[1];
    const float* z  = (const float*)d_in[2];
    const float* Wq = (const float*)d_in[3];
    const float* bq = (const float*)d_in[4];
    const float* Wk = (const float*)d_in[5];
    const float* bk = (const float*)d_in[6];
    const float* Wv = (const float*)d_in[7];
    const float* bv = (const float*)d_in[8];
    const float* Wp = (const float*)d_in[9];
    const float* bp = (const float*)d_in[10];

    float *q, *k, *v, *ao;
    cudaGetSymbolAddress((void**)&q,  g_q);
    cudaGetSymbolAddress((void**)&k,  g_k);
    cudaGetSymbolAddress((void**)&v,  g_v);
    cudaGetSymbolAddress((void**)&ao, g_ao);

    cudaFuncSetAttribute(attn_mma_kernel,
                         cudaFuncAttributeMaxDynamicSharedMemorySize, ATTN_SMEM_M);

    dim3 gGrid(DD / GBN, MM / GBM);   // (4, 64)
    gemm_bias_kernel<<<gGrid, 256>>>(x, Wq, bq, q);
    gemm_bias_kernel<<<gGrid, 256>>>(y, Wk, bk, k);
    gemm_bias_kernel<<<gGrid, 256>>>(z, Wv, bv, v);

    dim3 aGrid(SS / 64, BB * HH);     // (64, 16)
    attn_mma_kernel<<<aGrid, 128, ATTN_SMEM_M>>>(q, k, v, ao);

    gemm_bias_kernel<<<gGrid, 256>>>(ao, Wp, bp, (float*)d_out);
}